// round 2
// baseline (speedup 1.0000x reference)
#include <cuda_runtime.h>
#include <cuda_bf16.h>

// FeatureVectorInteractions: B=4096, N=128, D=64
// out[b] = < sum_i [VI0[b,i]>0] * V0[b,i,:] , sum_j [VI1[b,j]>0] * V1[b,j,:] >
//
// HBM-bound streaming reduction (~272 MB read, AI ~0.5 FLOP/B).
// One CTA per batch element, 256 threads = 16 row-groups (g) x 16 d-quads (q).
// Each thread accumulates float4 partials of u0,u1 over 8 rows (i = g + 16k);
// 16 consecutive lanes cover one 256B row -> fully coalesced 128B sectors.
// Masks hoisted to the loop front so ptxas batches all loads (high MLP_p1).
// Then smem reduce across row-groups, per-d product, warp dot-reduce.

#define NROWS 128
#define DDIM  64
#define DQ    16   // float4s per row
#define GROUPS 16
#define ROWS_PER_GROUP (NROWS / GROUPS)  // 8

__global__ __launch_bounds__(256, 8)
void fvi_kernel(const int* __restrict__ VI0,
                const int* __restrict__ VI1,
                const float* __restrict__ V0,
                const float* __restrict__ V1,
                float* __restrict__ out,
                int B)
{
    for (int b = blockIdx.x; b < B; b += gridDim.x) {
        const int t = threadIdx.x;
        const int g = t >> 4;    // row group 0..15
        const int q = t & 15;    // d-quad   0..15

        const float4* __restrict__ v0 =
            reinterpret_cast<const float4*>(V0) + (size_t)b * (NROWS * DQ);
        const float4* __restrict__ v1 =
            reinterpret_cast<const float4*>(V1) + (size_t)b * (NROWS * DQ);
        const int* __restrict__ vi0 = VI0 + (size_t)b * NROWS;
        const int* __restrict__ vi1 = VI1 + (size_t)b * NROWS;

        // Hoist all mask loads (broadcast across 16 lanes -> L1-friendly).
        float m0[ROWS_PER_GROUP], m1[ROWS_PER_GROUP];
        #pragma unroll
        for (int k = 0; k < ROWS_PER_GROUP; ++k) {
            const int i = g + k * GROUPS;
            m0[k] = (vi0[i] > 0) ? 1.0f : 0.0f;   // clip(int, 0, 1)
            m1[k] = (vi1[i] > 0) ? 1.0f : 0.0f;
        }

        float4 a0 = make_float4(0.f, 0.f, 0.f, 0.f);
        float4 a1 = make_float4(0.f, 0.f, 0.f, 0.f);

        #pragma unroll
        for (int k = 0; k < ROWS_PER_GROUP; ++k) {
            const int i = g + k * GROUPS;
            const float4 x0 = __ldg(&v0[i * DQ + q]);
            const float4 x1 = __ldg(&v1[i * DQ + q]);
            a0.x = fmaf(m0[k], x0.x, a0.x);
            a0.y = fmaf(m0[k], x0.y, a0.y);
            a0.z = fmaf(m0[k], x0.z, a0.z);
            a0.w = fmaf(m0[k], x0.w, a0.w);
            a1.x = fmaf(m1[k], x1.x, a1.x);
            a1.y = fmaf(m1[k], x1.y, a1.y);
            a1.z = fmaf(m1[k], x1.z, a1.z);
            a1.w = fmaf(m1[k], x1.w, a1.w);
        }

        // Stage 1: park per-(group, dquad) partials in smem.
        __shared__ float4 s0[GROUPS][DQ];   // [g][q] -> 4 d-lanes
        __shared__ float4 s1[GROUPS][DQ];
        __shared__ float sp[DDIM];

        s0[g][q] = a0;
        s1[g][q] = a1;
        __syncthreads();

        // Stage 2: threads 0..63 each own one d-lane; sum over 16 groups,
        // form u0[d]*u1[d].
        if (t < DDIM) {
            const int dq = t >> 2;       // which float4
            const int dl = t & 3;        // lane within float4
            float u0 = 0.f, u1 = 0.f;
            #pragma unroll
            for (int gg = 0; gg < GROUPS; ++gg) {
                const float* p0 = reinterpret_cast<const float*>(&s0[gg][dq]);
                const float* p1 = reinterpret_cast<const float*>(&s1[gg][dq]);
                u0 += p0[dl];
                u1 += p1[dl];
            }
            sp[t] = u0 * u1;
        }
        __syncthreads();

        // Stage 3: dot-reduce the 64 products.
        if (t < 32) {
            float v = sp[t] + sp[t + 32];
            #pragma unroll
            for (int off = 16; off > 0; off >>= 1)
                v += __shfl_down_sync(0xFFFFFFFFu, v, off);
            if (t == 0) out[b] = v;
        }
        __syncthreads();   // protect smem reuse across grid-stride iterations
    }
}

extern "C" void kernel_launch(void* const* d_in, const int* in_sizes, int n_in,
                              void* d_out, int out_size)
{
    const int*   VI0 = (const int*)d_in[0];
    const int*   VI1 = (const int*)d_in[1];
    const float* V0  = (const float*)d_in[2];
    const float* V1  = (const float*)d_in[3];
    float* out = (float*)d_out;

    const int B = in_sizes[0] / NROWS;  // 4096 for this problem
    fvi_kernel<<<B, 256>>>(VI0, VI1, V0, V1, out, B);
}